// round 14
// baseline (speedup 1.0000x reference)
#include <cuda_runtime.h>
#include <cuda_fp16.h>
#include <cstdint>

// ============================================================================
// Problem constants
// ============================================================================
#define NROWS 131072
#define LDIM  300
#define KTOT  608            // 600 padded to 608 = 19 chunks of 32
#define NCHUNKS 19
#define NCOLS 320            // 300 padded to 320

// SMEM layout (dynamic)
//  [0..256)      sdot[64] float
//  [512..1792)   b1s[320] float
//  [1792..3072)  w2s[320] float
//  [4096..)      Abuf: 2 stages x 5120    (64 rows x 80 B stride, 32 fp16 k)
//  [14336..)     Bbuf: 3 stages x 20992   (32 k-rows x 656 B stride, 320 fp16)
#define SD_DOT 0u
#define SD_B1  512u
#define SD_W2  1792u
#define A_OFF  4096u
#define A_STAGE 5120u
#define B_OFF  14336u
#define B_STAGE 20992u
#define B_ROW  656u
#define SMEM_TOTAL (14336u + 3u * 20992u)   // 77312 -> 2 CTAs/SM

// ============================================================================
// Device scratch
// ============================================================================
__device__ __align__(16) __half g_Bh[KTOT * NCOLS];
__device__ double        g_loss_sum;
__device__ unsigned int  g_cnt_pos, g_cnt_posr, g_cnt_negr;
__device__ unsigned int  g_ticket;

// ============================================================================
// PTX helpers
// ============================================================================
__device__ __forceinline__ uint32_t smem_u32(const void* p) {
    uint32_t a;
    asm("{ .reg .u64 t; cvta.to.shared.u64 t, %1; cvt.u32.u64 %0, t; }" : "=r"(a) : "l"(p));
    return a;
}
__device__ __forceinline__ void ldsm_x4(uint32_t* r, uint32_t addr) {
    asm volatile("ldmatrix.sync.aligned.m8n8.x4.shared.b16 {%0,%1,%2,%3}, [%4];"
        : "=r"(r[0]), "=r"(r[1]), "=r"(r[2]), "=r"(r[3]) : "r"(addr));
}
__device__ __forceinline__ void ldsm_x4_t(uint32_t* r, uint32_t addr) {
    asm volatile("ldmatrix.sync.aligned.m8n8.x4.trans.shared.b16 {%0,%1,%2,%3}, [%4];"
        : "=r"(r[0]), "=r"(r[1]), "=r"(r[2]), "=r"(r[3]) : "r"(addr));
}
__device__ __forceinline__ void mma16816h(float* c, const uint32_t* a, const uint32_t* b) {
    asm volatile("mma.sync.aligned.m16n8k16.row.col.f32.f16.f16.f32 "
        "{%0,%1,%2,%3}, {%4,%5,%6,%7}, {%8,%9}, {%0,%1,%2,%3};"
        : "+f"(c[0]), "+f"(c[1]), "+f"(c[2]), "+f"(c[3])
        : "r"(a[0]), "r"(a[1]), "r"(a[2]), "r"(a[3]), "r"(b[0]), "r"(b[1]));
}
#define CP_ASYNC16(dst, src) \
    asm volatile("cp.async.cg.shared.global [%0], [%1], 16;" :: "r"(dst), "l"(src) : "memory")
#define CP_COMMIT()  asm volatile("cp.async.commit_group;" ::: "memory")
#define CP_WAIT1()   asm volatile("cp.async.wait_group 1;" ::: "memory")
#define CP_WAIT0()   asm volatile("cp.async.wait_group 0;" ::: "memory")

// ============================================================================
// Kernel 1: prep — zero accumulators + ticket; build fp16 [k][n] image of W1
// Vectorized: each thread converts 4 consecutive n via one float4 load.
// ============================================================================
__global__ void prep_kernel(const float* __restrict__ w1) {
    int idx = blockIdx.x * blockDim.x + threadIdx.x;
    if (idx == 0) {
        g_loss_sum = 0.0; g_cnt_pos = 0u; g_cnt_posr = 0u; g_cnt_negr = 0u;
        g_ticket = 0u;
    }
    const int total = KTOT * (NCOLS / 4);   // 608 * 80 = 48640
    if (idx >= total) return;
    int k  = idx / (NCOLS / 4);
    int n4 = (idx % (NCOLS / 4)) * 4;
    float4 v = make_float4(0.f, 0.f, 0.f, 0.f);
    if (k < 2 * LDIM && n4 < LDIM)
        v = *(const float4*)(w1 + (size_t)k * LDIM + n4);
    __half2 h01 = __floats2half2_rn(v.x, v.y);
    __half2 h23 = __floats2half2_rn(v.z, v.w);
    uint2 packed;
    memcpy(&packed.x, &h01, 4);
    memcpy(&packed.y, &h23, 4);
    *(uint2*)(&g_Bh[(size_t)k * NCOLS + n4]) = packed;
}

// ============================================================================
// Kernel 2: fused GEMM (fp16 in, fp32 accum HMMA) + epilogue + last-CTA finalize
// CTA = 64 rows x 320 cols, warps 2M x 4N.
// ============================================================================
extern __shared__ __align__(128) unsigned char smem[];

__global__ void __launch_bounds__(256, 2) gemm_kernel(
    const float* __restrict__ sbj, const float* __restrict__ obj,
    const float* __restrict__ rlts,
    const float* __restrict__ spa_w, const float* __restrict__ spa_b,
    const float* __restrict__ b1, const float* __restrict__ w2, const float* __restrict__ b2,
    float* __restrict__ out, int out_size)
{
    const uint32_t sbase = smem_u32(smem);
    const int tid  = threadIdx.x;
    const int wid  = tid >> 5;
    const int lane = tid & 31;
    const int gid  = lane >> 2;
    const int tid4 = lane & 3;
    const int wm = wid >> 2;            // 0..1  (M dim)
    const int wn = wid & 3;             // 0..3  (N dim)
    const int m0 = wm * 32;
    const int n0 = wn * 80;
    const int row0 = blockIdx.x * 64;

    float* sdot = (float*)(smem + SD_DOT);
    float* b1s  = (float*)(smem + SD_B1);
    float* w2s  = (float*)(smem + SD_W2);
    for (int i = tid; i < NCOLS; i += 256) {
        b1s[i] = (i < LDIM) ? __ldg(&b1[i]) : 0.f;
        w2s[i] = (i < LDIM) ? __ldg(&w2[i]) : 0.f;
    }
    if (tid < 64) sdot[tid] = 0.f;
    __syncthreads();

    // A loader mapping: row = tid>>2 (0..63), k-offset = (tid&3)*8
    const int arow = tid >> 2;
    const int akq  = (tid & 3) * 8;
    const float* sbjRow = sbj + (size_t)(row0 + arow) * LDIM;
    const float* objRow = obj + (size_t)(row0 + arow) * LDIM;
    const uint32_t aStsOff = (uint32_t)(arow * 80 + akq * 2);

    // ldmatrix lane offsets
    const uint32_t aoff = (uint32_t)((lane & 15) * 80 + ((lane >> 4) & 1) * 16);
    const uint32_t boff = (uint32_t)((((lane >> 3) & 1) * 8 + (lane & 7)) * B_ROW + ((lane >> 4) & 1) * 16);

    float4 x[2];   // A prefetch registers (8 floats)

    float acc[2][10][4];
    #pragma unroll
    for (int mi = 0; mi < 2; mi++)
        #pragma unroll
        for (int ni = 0; ni < 10; ni++)
            #pragma unroll
            for (int q = 0; q < 4; q++) acc[mi][ni][q] = 0.f;

    // -------- helpers --------
    auto cpB = [&](int c, int bs) {
        // chunk c: 32 k-rows x 320 fp16 = 1280 16B segments
        const uint32_t dstBase = sbase + B_OFF + (uint32_t)bs * B_STAGE;
        #pragma unroll
        for (int j = 0; j < 5; j++) {
            int s  = tid + j * 256;          // 0..1279
            int r  = s / 40;                 // 0..31
            int sg = s % 40;                 // 0..39
            const __half* src = g_Bh + ((size_t)(c * 32 + r) * NCOLS + sg * 8);
            uint32_t dst = dstBase + (uint32_t)(r * B_ROW + sg * 16);
            CP_ASYNC16(dst, src);
        }
    };
    auto ldgA = [&](int c) {
        #pragma unroll
        for (int j = 0; j < 2; j++) {
            int kg = c * 32 + akq + j * 4;
            float4 v = make_float4(0.f, 0.f, 0.f, 0.f);
            if (kg < LDIM)           v = *(const float4*)(sbjRow + kg);
            else if (kg < 2 * LDIM)  v = *(const float4*)(objRow + (kg - LDIM));
            x[j] = v;
        }
    };
    auto stsA = [&](int as) {
        const uint32_t dstA = sbase + A_OFF + (uint32_t)as * A_STAGE + aStsOff;
        uint32_t hw[4];
        #pragma unroll
        for (int j = 0; j < 2; j++) {
            float v0 = fmaxf(x[j].x, 0.f), v1 = fmaxf(x[j].y, 0.f);
            float v2 = fmaxf(x[j].z, 0.f), v3 = fmaxf(x[j].w, 0.f);
            __half2 p01 = __floats2half2_rn(v0, v1);
            __half2 p23 = __floats2half2_rn(v2, v3);
            memcpy(&hw[j * 2],     &p01, 4);
            memcpy(&hw[j * 2 + 1], &p23, 4);
        }
        asm volatile("st.shared.v4.b32 [%0], {%1,%2,%3,%4};" ::
            "r"(dstA), "r"(hw[0]), "r"(hw[1]), "r"(hw[2]), "r"(hw[3]));
    };

    // -------- pipeline prologue --------
    cpB(0, 0); CP_COMMIT();
    cpB(1, 1); CP_COMMIT();
    ldgA(0);
    stsA(0);
    ldgA(1);
    CP_WAIT1();          // B(0) resident
    __syncthreads();

    // -------- main K loop --------
    #pragma unroll 1
    for (int c = 0; c < NCHUNKS; c++) {
        const int as = c & 1;
        const int bs = c % 3;
        const uint32_t AH = sbase + A_OFF + (uint32_t)as * A_STAGE + (uint32_t)(m0 * 80) + aoff;
        const uint32_t BH = sbase + B_OFF + (uint32_t)bs * B_STAGE + (uint32_t)(n0 * 2) + boff;

        // Preload A fragments for BOTH k16 halves of this 32-deep chunk
        uint32_t ah[16];
        ldsm_x4(ah,      AH);               // ks0, mi0
        ldsm_x4(ah + 4,  AH + 1280);        // ks0, mi1
        ldsm_x4(ah + 8,  AH + 32);          // ks1, mi0
        ldsm_x4(ah + 12, AH + 1280 + 32);   // ks1, mi1

        #pragma unroll
        for (int g = 0; g < 5; g++) {
            uint32_t bh[8];
            ldsm_x4_t(bh,     BH + g * 32);                 // ks0
            ldsm_x4_t(bh + 4, BH + g * 32 + 16 * B_ROW);    // ks1
            #pragma unroll
            for (int mi = 0; mi < 2; mi++) {
                #pragma unroll
                for (int q = 0; q < 2; q++) {
                    float* C = acc[mi][2 * g + q];
                    mma16816h(C, ah + mi * 4,     bh + q * 2);
                    mma16816h(C, ah + 8 + mi * 4, bh + 4 + q * 2);
                }
            }
        }
        if (c + 1 < NCHUNKS) stsA((c + 1) & 1);
        if (c + 2 < NCHUNKS) {
            ldgA(c + 2);
            cpB(c + 2, (c + 2) % 3); CP_COMMIT();
            CP_WAIT1();
        } else {
            CP_WAIT0();
        }
        __syncthreads();
    }

    // -------- epilogue: bias + relu + w2 dot --------
    {
        float p[2][2];
        p[0][0] = p[0][1] = p[1][0] = p[1][1] = 0.f;
        #pragma unroll
        for (int ni = 0; ni < 10; ni++) {
            int gcol = n0 + ni * 8 + tid4 * 2;
            float w2a = w2s[gcol], w2b = w2s[gcol + 1];
            float b1a = b1s[gcol], b1b = b1s[gcol + 1];
            #pragma unroll
            for (int mi = 0; mi < 2; mi++) {
                float* C = acc[mi][ni];
                p[mi][0] = fmaf(fmaxf(C[0] + b1a, 0.f), w2a,
                            fmaf(fmaxf(C[1] + b1b, 0.f), w2b, p[mi][0]));
                p[mi][1] = fmaf(fmaxf(C[2] + b1a, 0.f), w2a,
                            fmaf(fmaxf(C[3] + b1b, 0.f), w2b, p[mi][1]));
            }
        }
        #pragma unroll
        for (int mi = 0; mi < 2; mi++)
            #pragma unroll
            for (int h = 0; h < 2; h++) {
                p[mi][h] += __shfl_xor_sync(0xFFFFFFFFu, p[mi][h], 1);
                p[mi][h] += __shfl_xor_sync(0xFFFFFFFFu, p[mi][h], 2);
            }
        if (tid4 == 0) {
            #pragma unroll
            for (int mi = 0; mi < 2; mi++)
                #pragma unroll
                for (int h = 0; h < 2; h++)
                    atomicAdd(&sdot[m0 + mi * 16 + h * 8 + gid], p[mi][h]);
        }
    }
    __syncthreads();

    // -------- final epilogue --------
    if (tid < 64) {
        const int r = tid;
        const int i = row0 + r;
        float lan = sdot[r] + __ldg(&b2[0]);

        const float* rp = rlts + (size_t)i * 15;
        float label = rp[4];
        float sx1 = rp[5],  sy1 = rp[6],  sx2 = rp[7],  sy2 = rp[8];
        float ox1 = rp[10], oy1 = rp[11], ox2 = rp[12], oy2 = rp[13];
        float sw = sx2 - sx1, sh = sy2 - sy1, ow = ox2 - ox1, oh = oy2 - oy1;
        float box = __ldg(&spa_b[0]);
        box += ((sx1 - ox1) / sw) * __ldg(&spa_w[0]);
        box += ((sy1 - oy1) / sh) * __ldg(&spa_w[1]);
        box += logf(sw / ow)      * __ldg(&spa_w[2]);
        box += logf(sh / oh)      * __ldg(&spa_w[3]);
        box += ((ox1 - sx1) / ow) * __ldg(&spa_w[4]);
        box += ((oy1 - sy1) / oh) * __ldg(&spa_w[5]);
        box += logf(ow / sw)      * __ldg(&spa_w[6]);
        box += logf(oh / sh)      * __ldg(&spa_w[7]);

        float xs = lan + box;
        float sc = 1.f / (1.f + expf(-xs));
        out[i] = sc;

        bool pos = label > 0.f;
        float log_s  = fmaxf(logf(fmaxf(sc,       1e-12f)), -100.f);
        float log_1s = fmaxf(logf(fmaxf(1.f - sc, 1e-12f)), -100.f);
        float term = -(pos ? log_s : log_1s);

        unsigned m_pos  = __ballot_sync(0xFFFFFFFFu, pos);
        unsigned m_posr = __ballot_sync(0xFFFFFFFFu, (!pos) && (sc >= 0.5f));
        unsigned m_negr = __ballot_sync(0xFFFFFFFFu, pos && (sc < 0.5f));
        #pragma unroll
        for (int o = 16; o > 0; o >>= 1) term += __shfl_xor_sync(0xFFFFFFFFu, term, o);
        if ((tid & 31) == 0) {
            atomicAdd(&g_cnt_pos,  (unsigned)__popc(m_pos));
            atomicAdd(&g_cnt_posr, (unsigned)__popc(m_posr));
            atomicAdd(&g_cnt_negr, (unsigned)__popc(m_negr));
            atomicAdd(&g_loss_sum, (double)term);
        }
    }

    // -------- last-CTA finalize (replaces separate kernel) --------
    __shared__ int sIsLast;
    __syncthreads();
    if (tid == 0) {
        __threadfence();
        unsigned t = atomicAdd(&g_ticket, 1u);
        sIsLast = (t == gridDim.x - 1) ? 1 : 0;
    }
    __syncthreads();
    if (sIsLast) {
        if (tid == 0 && out_size >= NROWS + 4) {
            float Npos  = (float)g_cnt_pos;
            float Nneg  = (float)(NROWS - (int)g_cnt_pos);
            float Nposr = (float)g_cnt_posr;
            float Nnegr = (float)g_cnt_negr;
            out[NROWS + 0] = (float)(g_loss_sum / (double)NROWS);
            out[NROWS + 1] = Nposr / Npos;
            out[NROWS + 2] = Nnegr / Nneg;
            out[NROWS + 3] = (Nposr + Nnegr) / (Npos + Nneg);
        }
        for (int idx = NROWS + 4 + tid; idx < out_size; idx += 256)
            out[idx] = 0.f;
    }
}

// ============================================================================
// Launch
// ============================================================================
extern "C" void kernel_launch(void* const* d_in, const int* in_sizes, int n_in,
                              void* d_out, int out_size) {
    const float* sbj   = (const float*)d_in[0];
    const float* obj   = (const float*)d_in[1];
    const float* rlts  = (const float*)d_in[2];
    const float* spa_w = (const float*)d_in[3];
    const float* spa_b = (const float*)d_in[4];
    const float* w1    = (const float*)d_in[5];
    const float* b1    = (const float*)d_in[6];
    const float* w2    = (const float*)d_in[7];
    const float* b2    = (const float*)d_in[8];
    float* out = (float*)d_out;

    cudaFuncSetAttribute(gemm_kernel, cudaFuncAttributeMaxDynamicSharedMemorySize, SMEM_TOTAL);

    const int prep_total = KTOT * (NCOLS / 4);
    prep_kernel<<<(prep_total + 255) / 256, 256>>>(w1);
    gemm_kernel<<<NROWS / 64, 256, SMEM_TOTAL>>>(sbj, obj, rlts, spa_w, spa_b, b1, w2, b2, out, out_size);
}

// round 15
// speedup vs baseline: 1.0675x; 1.0675x over previous
#include <cuda_runtime.h>
#include <cuda_fp16.h>
#include <cstdint>

// ============================================================================
// Problem constants
// ============================================================================
#define NROWS 131072
#define LDIM  300
#define KTOT  608            // 600 padded to 608 = 19 chunks of 32
#define NCHUNKS 19
#define NCOLS 320            // 300 padded to 320

// SMEM layout (dynamic)
//  [0..256)      sdot[64] float
//  [512..1792)   b1s[320] float
//  [1792..3072)  w2s[320] float
//  [4096..)      Abuf: 2 stages x 5120    (64 rows x 80 B stride, 32 fp16 k)
//  [14336..)     Bbuf: 3 stages x 20992   (32 k-rows x 656 B stride, 320 fp16)
#define SD_DOT 0u
#define SD_B1  512u
#define SD_W2  1792u
#define A_OFF  4096u
#define A_STAGE 5120u
#define B_OFF  14336u
#define B_STAGE 20992u
#define B_ROW  656u
#define SMEM_TOTAL (14336u + 3u * 20992u)   // 77312 -> 2 CTAs/SM

// ============================================================================
// Device scratch
// ============================================================================
__device__ __align__(16) __half g_Bh[KTOT * NCOLS];
__device__ double        g_loss_sum;
__device__ unsigned int  g_cnt_pos, g_cnt_posr, g_cnt_negr;

// ============================================================================
// PTX helpers
// ============================================================================
__device__ __forceinline__ uint32_t smem_u32(const void* p) {
    uint32_t a;
    asm("{ .reg .u64 t; cvta.to.shared.u64 t, %1; cvt.u32.u64 %0, t; }" : "=r"(a) : "l"(p));
    return a;
}
__device__ __forceinline__ void ldsm_x4(uint32_t* r, uint32_t addr) {
    asm volatile("ldmatrix.sync.aligned.m8n8.x4.shared.b16 {%0,%1,%2,%3}, [%4];"
        : "=r"(r[0]), "=r"(r[1]), "=r"(r[2]), "=r"(r[3]) : "r"(addr));
}
__device__ __forceinline__ void ldsm_x4_t(uint32_t* r, uint32_t addr) {
    asm volatile("ldmatrix.sync.aligned.m8n8.x4.trans.shared.b16 {%0,%1,%2,%3}, [%4];"
        : "=r"(r[0]), "=r"(r[1]), "=r"(r[2]), "=r"(r[3]) : "r"(addr));
}
__device__ __forceinline__ void mma16816h(float* c, const uint32_t* a, const uint32_t* b) {
    asm volatile("mma.sync.aligned.m16n8k16.row.col.f32.f16.f16.f32 "
        "{%0,%1,%2,%3}, {%4,%5,%6,%7}, {%8,%9}, {%0,%1,%2,%3};"
        : "+f"(c[0]), "+f"(c[1]), "+f"(c[2]), "+f"(c[3])
        : "r"(a[0]), "r"(a[1]), "r"(a[2]), "r"(a[3]), "r"(b[0]), "r"(b[1]));
}
#define CP_ASYNC16(dst, src) \
    asm volatile("cp.async.cg.shared.global [%0], [%1], 16;" :: "r"(dst), "l"(src) : "memory")
#define CP_COMMIT()  asm volatile("cp.async.commit_group;" ::: "memory")
#define CP_WAIT1()   asm volatile("cp.async.wait_group 1;" ::: "memory")
#define CP_WAIT0()   asm volatile("cp.async.wait_group 0;" ::: "memory")

// ============================================================================
// Kernel 1: prep — zero accumulators; build fp16 [k][n] image of W1
// Vectorized: each thread converts 4 consecutive n via one float4 load.
// ============================================================================
__global__ void prep_kernel(const float* __restrict__ w1) {
    int idx = blockIdx.x * blockDim.x + threadIdx.x;
    if (idx == 0) {
        g_loss_sum = 0.0; g_cnt_pos = 0u; g_cnt_posr = 0u; g_cnt_negr = 0u;
    }
    const int total = KTOT * (NCOLS / 4);   // 608 * 80 = 48640
    if (idx >= total) return;
    int k  = idx / (NCOLS / 4);
    int n4 = (idx % (NCOLS / 4)) * 4;
    float4 v = make_float4(0.f, 0.f, 0.f, 0.f);
    if (k < 2 * LDIM && n4 < LDIM)
        v = *(const float4*)(w1 + (size_t)k * LDIM + n4);
    __half2 h01 = __floats2half2_rn(v.x, v.y);
    __half2 h23 = __floats2half2_rn(v.z, v.w);
    uint2 packed;
    memcpy(&packed.x, &h01, 4);
    memcpy(&packed.y, &h23, 4);
    *(uint2*)(&g_Bh[(size_t)k * NCOLS + n4]) = packed;
}

// ============================================================================
// Kernel 2: fused GEMM (fp16 in, fp32 accum HMMA) + epilogue
// CTA = 64 rows x 320 cols, warps 2M x 4N.
// ============================================================================
extern __shared__ __align__(128) unsigned char smem[];

__global__ void __launch_bounds__(256, 2) gemm_kernel(
    const float* __restrict__ sbj, const float* __restrict__ obj,
    const float* __restrict__ rlts,
    const float* __restrict__ spa_w, const float* __restrict__ spa_b,
    const float* __restrict__ b1, const float* __restrict__ w2, const float* __restrict__ b2,
    float* __restrict__ out)
{
    const uint32_t sbase = smem_u32(smem);
    const int tid  = threadIdx.x;
    const int wid  = tid >> 5;
    const int lane = tid & 31;
    const int gid  = lane >> 2;
    const int tid4 = lane & 3;
    const int wm = wid >> 2;            // 0..1  (M dim)
    const int wn = wid & 3;             // 0..3  (N dim)
    const int m0 = wm * 32;
    const int n0 = wn * 80;
    const int row0 = blockIdx.x * 64;

    float* sdot = (float*)(smem + SD_DOT);
    float* b1s  = (float*)(smem + SD_B1);
    float* w2s  = (float*)(smem + SD_W2);
    for (int i = tid; i < NCOLS; i += 256) {
        b1s[i] = (i < LDIM) ? __ldg(&b1[i]) : 0.f;
        w2s[i] = (i < LDIM) ? __ldg(&w2[i]) : 0.f;
    }
    if (tid < 64) sdot[tid] = 0.f;
    __syncthreads();

    // A loader mapping: row = tid>>2 (0..63), k-offset = (tid&3)*8
    const int arow = tid >> 2;
    const int akq  = (tid & 3) * 8;
    const float* sbjRow = sbj + (size_t)(row0 + arow) * LDIM;
    const float* objRow = obj + (size_t)(row0 + arow) * LDIM;
    const uint32_t aStsOff = (uint32_t)(arow * 80 + akq * 2);

    // ldmatrix lane offsets
    const uint32_t aoff = (uint32_t)((lane & 15) * 80 + ((lane >> 4) & 1) * 16);
    const uint32_t boff = (uint32_t)((((lane >> 3) & 1) * 8 + (lane & 7)) * B_ROW + ((lane >> 4) & 1) * 16);

    float4 x[2];   // A prefetch registers (8 floats)

    float acc[2][10][4];
    #pragma unroll
    for (int mi = 0; mi < 2; mi++)
        #pragma unroll
        for (int ni = 0; ni < 10; ni++)
            #pragma unroll
            for (int q = 0; q < 4; q++) acc[mi][ni][q] = 0.f;

    // -------- helpers --------
    auto cpB = [&](int c, int bs) {
        // chunk c: 32 k-rows x 320 fp16 = 1280 16B segments
        const uint32_t dstBase = sbase + B_OFF + (uint32_t)bs * B_STAGE;
        #pragma unroll
        for (int j = 0; j < 5; j++) {
            int s  = tid + j * 256;          // 0..1279
            int r  = s / 40;                 // 0..31
            int sg = s % 40;                 // 0..39
            const __half* src = g_Bh + ((size_t)(c * 32 + r) * NCOLS + sg * 8);
            uint32_t dst = dstBase + (uint32_t)(r * B_ROW + sg * 16);
            CP_ASYNC16(dst, src);
        }
    };
    auto ldgA = [&](int c) {
        #pragma unroll
        for (int j = 0; j < 2; j++) {
            int kg = c * 32 + akq + j * 4;
            float4 v = make_float4(0.f, 0.f, 0.f, 0.f);
            if (kg < LDIM)           v = *(const float4*)(sbjRow + kg);
            else if (kg < 2 * LDIM)  v = *(const float4*)(objRow + (kg - LDIM));
            x[j] = v;
        }
    };
    auto stsA = [&](int as) {
        const uint32_t dstA = sbase + A_OFF + (uint32_t)as * A_STAGE + aStsOff;
        uint32_t hw[4];
        #pragma unroll
        for (int j = 0; j < 2; j++) {
            float v0 = fmaxf(x[j].x, 0.f), v1 = fmaxf(x[j].y, 0.f);
            float v2 = fmaxf(x[j].z, 0.f), v3 = fmaxf(x[j].w, 0.f);
            __half2 p01 = __floats2half2_rn(v0, v1);
            __half2 p23 = __floats2half2_rn(v2, v3);
            memcpy(&hw[j * 2],     &p01, 4);
            memcpy(&hw[j * 2 + 1], &p23, 4);
        }
        asm volatile("st.shared.v4.b32 [%0], {%1,%2,%3,%4};" ::
            "r"(dstA), "r"(hw[0]), "r"(hw[1]), "r"(hw[2]), "r"(hw[3]));
    };

    // -------- pipeline prologue --------
    cpB(0, 0); CP_COMMIT();
    cpB(1, 1); CP_COMMIT();
    ldgA(0);
    stsA(0);
    ldgA(1);
    CP_WAIT1();          // B(0) resident
    __syncthreads();

    // -------- main K loop --------
    #pragma unroll 1
    for (int c = 0; c < NCHUNKS; c++) {
        const int as = c & 1;
        const int bs = c % 3;
        const uint32_t AH = sbase + A_OFF + (uint32_t)as * A_STAGE + (uint32_t)(m0 * 80) + aoff;
        const uint32_t BH = sbase + B_OFF + (uint32_t)bs * B_STAGE + (uint32_t)(n0 * 2) + boff;

        // Preload A fragments for BOTH k16 halves of this 32-deep chunk
        uint32_t ah[16];
        ldsm_x4(ah,      AH);               // ks0, mi0
        ldsm_x4(ah + 4,  AH + 1280);        // ks0, mi1
        ldsm_x4(ah + 8,  AH + 32);          // ks1, mi0
        ldsm_x4(ah + 12, AH + 1280 + 32);   // ks1, mi1

        #pragma unroll
        for (int g = 0; g < 5; g++) {
            uint32_t bh[8];
            ldsm_x4_t(bh,     BH + g * 32);                 // ks0
            ldsm_x4_t(bh + 4, BH + g * 32 + 16 * B_ROW);    // ks1
            #pragma unroll
            for (int mi = 0; mi < 2; mi++) {
                #pragma unroll
                for (int q = 0; q < 2; q++) {
                    float* C = acc[mi][2 * g + q];
                    mma16816h(C, ah + mi * 4,     bh + q * 2);
                    mma16816h(C, ah + 8 + mi * 4, bh + 4 + q * 2);
                }
            }
        }
        if (c + 1 < NCHUNKS) stsA((c + 1) & 1);
        if (c + 2 < NCHUNKS) {
            ldgA(c + 2);
            cpB(c + 2, (c + 2) % 3); CP_COMMIT();
            CP_WAIT1();
        } else {
            CP_WAIT0();
        }
        __syncthreads();
    }

    // -------- epilogue: bias + relu + w2 dot --------
    {
        float p[2][2];
        p[0][0] = p[0][1] = p[1][0] = p[1][1] = 0.f;
        #pragma unroll
        for (int ni = 0; ni < 10; ni++) {
            int gcol = n0 + ni * 8 + tid4 * 2;
            float w2a = w2s[gcol], w2b = w2s[gcol + 1];
            float b1a = b1s[gcol], b1b = b1s[gcol + 1];
            #pragma unroll
            for (int mi = 0; mi < 2; mi++) {
                float* C = acc[mi][ni];
                p[mi][0] = fmaf(fmaxf(C[0] + b1a, 0.f), w2a,
                            fmaf(fmaxf(C[1] + b1b, 0.f), w2b, p[mi][0]));
                p[mi][1] = fmaf(fmaxf(C[2] + b1a, 0.f), w2a,
                            fmaf(fmaxf(C[3] + b1b, 0.f), w2b, p[mi][1]));
            }
        }
        #pragma unroll
        for (int mi = 0; mi < 2; mi++)
            #pragma unroll
            for (int h = 0; h < 2; h++) {
                p[mi][h] += __shfl_xor_sync(0xFFFFFFFFu, p[mi][h], 1);
                p[mi][h] += __shfl_xor_sync(0xFFFFFFFFu, p[mi][h], 2);
            }
        if (tid4 == 0) {
            #pragma unroll
            for (int mi = 0; mi < 2; mi++)
                #pragma unroll
                for (int h = 0; h < 2; h++)
                    atomicAdd(&sdot[m0 + mi * 16 + h * 8 + gid], p[mi][h]);
        }
    }
    __syncthreads();

    // -------- final epilogue --------
    if (tid < 64) {
        const int r = tid;
        const int i = row0 + r;
        float lan = sdot[r] + __ldg(&b2[0]);

        const float* rp = rlts + (size_t)i * 15;
        float label = rp[4];
        float sx1 = rp[5],  sy1 = rp[6],  sx2 = rp[7],  sy2 = rp[8];
        float ox1 = rp[10], oy1 = rp[11], ox2 = rp[12], oy2 = rp[13];
        float sw = sx2 - sx1, sh = sy2 - sy1, ow = ox2 - ox1, oh = oy2 - oy1;
        float box = __ldg(&spa_b[0]);
        box += ((sx1 - ox1) / sw) * __ldg(&spa_w[0]);
        box += ((sy1 - oy1) / sh) * __ldg(&spa_w[1]);
        box += logf(sw / ow)      * __ldg(&spa_w[2]);
        box += logf(sh / oh)      * __ldg(&spa_w[3]);
        box += ((ox1 - sx1) / ow) * __ldg(&spa_w[4]);
        box += ((oy1 - sy1) / oh) * __ldg(&spa_w[5]);
        box += logf(ow / sw)      * __ldg(&spa_w[6]);
        box += logf(oh / sh)      * __ldg(&spa_w[7]);

        float xs = lan + box;
        float sc = 1.f / (1.f + expf(-xs));
        out[i] = sc;

        bool pos = label > 0.f;
        float log_s  = fmaxf(logf(fmaxf(sc,       1e-12f)), -100.f);
        float log_1s = fmaxf(logf(fmaxf(1.f - sc, 1e-12f)), -100.f);
        float term = -(pos ? log_s : log_1s);

        unsigned m_pos  = __ballot_sync(0xFFFFFFFFu, pos);
        unsigned m_posr = __ballot_sync(0xFFFFFFFFu, (!pos) && (sc >= 0.5f));
        unsigned m_negr = __ballot_sync(0xFFFFFFFFu, pos && (sc < 0.5f));
        #pragma unroll
        for (int o = 16; o > 0; o >>= 1) term += __shfl_xor_sync(0xFFFFFFFFu, term, o);
        if ((tid & 31) == 0) {
            atomicAdd(&g_cnt_pos,  (unsigned)__popc(m_pos));
            atomicAdd(&g_cnt_posr, (unsigned)__popc(m_posr));
            atomicAdd(&g_cnt_negr, (unsigned)__popc(m_negr));
            atomicAdd(&g_loss_sum, (double)term);
        }
    }
}

// ============================================================================
// Kernel 3: finalize
// ============================================================================
__global__ void finalize_kernel(float* __restrict__ out, int out_size) {
    if (threadIdx.x == 0 && blockIdx.x == 0) {
        float Npos  = (float)g_cnt_pos;
        float Nneg  = (float)(NROWS - (int)g_cnt_pos);
        float Nposr = (float)g_cnt_posr;
        float Nnegr = (float)g_cnt_negr;
        float loss  = (float)(g_loss_sum / (double)NROWS);
        if (out_size >= NROWS + 4) {
            out[NROWS + 0] = loss;
            out[NROWS + 1] = Nposr / Npos;
            out[NROWS + 2] = Nnegr / Nneg;
            out[NROWS + 3] = (Nposr + Nnegr) / (Npos + Nneg);
        }
    }
    int idx = NROWS + 4 + (int)(blockIdx.x * blockDim.x + threadIdx.x);
    if (idx < out_size) out[idx] = 0.f;
}

// ============================================================================
// Launch
// ============================================================================
extern "C" void kernel_launch(void* const* d_in, const int* in_sizes, int n_in,
                              void* d_out, int out_size) {
    const float* sbj   = (const float*)d_in[0];
    const float* obj   = (const float*)d_in[1];
    const float* rlts  = (const float*)d_in[2];
    const float* spa_w = (const float*)d_in[3];
    const float* spa_b = (const float*)d_in[4];
    const float* w1    = (const float*)d_in[5];
    const float* b1    = (const float*)d_in[6];
    const float* w2    = (const float*)d_in[7];
    const float* b2    = (const float*)d_in[8];
    float* out = (float*)d_out;

    cudaFuncSetAttribute(gemm_kernel, cudaFuncAttributeMaxDynamicSharedMemorySize, SMEM_TOTAL);

    const int prep_total = KTOT * (NCOLS / 4);
    prep_kernel<<<(prep_total + 255) / 256, 256>>>(w1);
    gemm_kernel<<<NROWS / 64, 256, SMEM_TOTAL>>>(sbj, obj, rlts, spa_w, spa_b, b1, w2, b2, out);
    finalize_kernel<<<1, 256>>>(out, out_size);
}

// round 16
// speedup vs baseline: 1.0737x; 1.0058x over previous
#include <cuda_runtime.h>
#include <cuda_fp16.h>
#include <cstdint>

// ============================================================================
// Problem constants
// ============================================================================
#define NROWS 131072
#define LDIM  300
#define KTOT  608            // 600 padded to 608 = 19 chunks of 32
#define NCHUNKS 19
#define NCOLS 320            // 300 padded to 320

// SMEM layout (dynamic)
//  [0..256)      sdot[64] float
//  [512..1792)   b1s[320] float
//  [1792..3072)  w2s[320] float
//  [4096..)      Abuf: 2 stages x 5120    (64 rows x 80 B stride, 32 fp16 k)
//  [14336..)     Bbuf: 3 stages x 20992   (32 k-rows x 656 B stride, 320 fp16)
#define SD_DOT 0u
#define SD_B1  512u
#define SD_W2  1792u
#define A_OFF  4096u
#define A_STAGE 5120u
#define B_OFF  14336u
#define B_STAGE 20992u
#define B_ROW  656u
#define SMEM_TOTAL (14336u + 3u * 20992u)   // 77312 -> 2 CTAs/SM

// ============================================================================
// Device scratch
// ============================================================================
__device__ __align__(16) __half g_Bh[KTOT * NCOLS];
__device__ double        g_loss_sum;
__device__ unsigned int  g_cnt_pos, g_cnt_posr, g_cnt_negr;

// ============================================================================
// PTX helpers
// ============================================================================
__device__ __forceinline__ uint32_t smem_u32(const void* p) {
    uint32_t a;
    asm("{ .reg .u64 t; cvta.to.shared.u64 t, %1; cvt.u32.u64 %0, t; }" : "=r"(a) : "l"(p));
    return a;
}
__device__ __forceinline__ void ldsm_x4(uint32_t* r, uint32_t addr) {
    asm volatile("ldmatrix.sync.aligned.m8n8.x4.shared.b16 {%0,%1,%2,%3}, [%4];"
        : "=r"(r[0]), "=r"(r[1]), "=r"(r[2]), "=r"(r[3]) : "r"(addr));
}
__device__ __forceinline__ void ldsm_x4_t(uint32_t* r, uint32_t addr) {
    asm volatile("ldmatrix.sync.aligned.m8n8.x4.trans.shared.b16 {%0,%1,%2,%3}, [%4];"
        : "=r"(r[0]), "=r"(r[1]), "=r"(r[2]), "=r"(r[3]) : "r"(addr));
}
__device__ __forceinline__ void mma16816h(float* c, const uint32_t* a, const uint32_t* b) {
    asm volatile("mma.sync.aligned.m16n8k16.row.col.f32.f16.f16.f32 "
        "{%0,%1,%2,%3}, {%4,%5,%6,%7}, {%8,%9}, {%0,%1,%2,%3};"
        : "+f"(c[0]), "+f"(c[1]), "+f"(c[2]), "+f"(c[3])
        : "r"(a[0]), "r"(a[1]), "r"(a[2]), "r"(a[3]), "r"(b[0]), "r"(b[1]));
}
#define CP_ASYNC16(dst, src) \
    asm volatile("cp.async.cg.shared.global [%0], [%1], 16;" :: "r"(dst), "l"(src) : "memory")
#define CP_COMMIT()  asm volatile("cp.async.commit_group;" ::: "memory")
#define CP_WAIT1()   asm volatile("cp.async.wait_group 1;" ::: "memory")
#define CP_WAIT0()   asm volatile("cp.async.wait_group 0;" ::: "memory")

// ============================================================================
// Kernel 1: prep — zero accumulators; build fp16 [k][n] image of W1
// ============================================================================
__global__ void prep_kernel(const float* __restrict__ w1) {
    int idx = blockIdx.x * blockDim.x + threadIdx.x;
    if (idx == 0) {
        g_loss_sum = 0.0; g_cnt_pos = 0u; g_cnt_posr = 0u; g_cnt_negr = 0u;
    }
    const int total = KTOT * (NCOLS / 4);   // 608 * 80 = 48640
    if (idx >= total) return;
    int k  = idx / (NCOLS / 4);
    int n4 = (idx % (NCOLS / 4)) * 4;
    float4 v = make_float4(0.f, 0.f, 0.f, 0.f);
    if (k < 2 * LDIM && n4 < LDIM)
        v = *(const float4*)(w1 + (size_t)k * LDIM + n4);
    __half2 h01 = __floats2half2_rn(v.x, v.y);
    __half2 h23 = __floats2half2_rn(v.z, v.w);
    uint2 packed;
    memcpy(&packed.x, &h01, 4);
    memcpy(&packed.y, &h23, 4);
    *(uint2*)(&g_Bh[(size_t)k * NCOLS + n4]) = packed;
}

// ============================================================================
// Kernel 2: fused GEMM (fp16 in, fp32 accum HMMA) + epilogue
// CTA = 64 rows x 320 cols, warps 2M x 4N.
// Inner loop: all ks0 MMAs before ks1 MMAs -> C-reuse distance 4 (was 1).
// ============================================================================
extern __shared__ __align__(128) unsigned char smem[];

__global__ void __launch_bounds__(256, 2) gemm_kernel(
    const float* __restrict__ sbj, const float* __restrict__ obj,
    const float* __restrict__ rlts,
    const float* __restrict__ spa_w, const float* __restrict__ spa_b,
    const float* __restrict__ b1, const float* __restrict__ w2, const float* __restrict__ b2,
    float* __restrict__ out)
{
    const uint32_t sbase = smem_u32(smem);
    const int tid  = threadIdx.x;
    const int wid  = tid >> 5;
    const int lane = tid & 31;
    const int gid  = lane >> 2;
    const int tid4 = lane & 3;
    const int wm = wid >> 2;            // 0..1  (M dim)
    const int wn = wid & 3;             // 0..3  (N dim)
    const int m0 = wm * 32;
    const int n0 = wn * 80;
    const int row0 = blockIdx.x * 64;

    float* sdot = (float*)(smem + SD_DOT);
    float* b1s  = (float*)(smem + SD_B1);
    float* w2s  = (float*)(smem + SD_W2);
    for (int i = tid; i < NCOLS; i += 256) {
        b1s[i] = (i < LDIM) ? __ldg(&b1[i]) : 0.f;
        w2s[i] = (i < LDIM) ? __ldg(&w2[i]) : 0.f;
    }
    if (tid < 64) sdot[tid] = 0.f;
    __syncthreads();

    // A loader mapping: row = tid>>2 (0..63), k-offset = (tid&3)*8
    const int arow = tid >> 2;
    const int akq  = (tid & 3) * 8;
    const float* sbjRow = sbj + (size_t)(row0 + arow) * LDIM;
    const float* objRow = obj + (size_t)(row0 + arow) * LDIM;
    const uint32_t aStsOff = (uint32_t)(arow * 80 + akq * 2);

    // ldmatrix lane offsets
    const uint32_t aoff = (uint32_t)((lane & 15) * 80 + ((lane >> 4) & 1) * 16);
    const uint32_t boff = (uint32_t)((((lane >> 3) & 1) * 8 + (lane & 7)) * B_ROW + ((lane >> 4) & 1) * 16);

    float4 x[2];   // A prefetch registers (8 floats)

    float acc[2][10][4];
    #pragma unroll
    for (int mi = 0; mi < 2; mi++)
        #pragma unroll
        for (int ni = 0; ni < 10; ni++)
            #pragma unroll
            for (int q = 0; q < 4; q++) acc[mi][ni][q] = 0.f;

    // -------- helpers --------
    auto cpB = [&](int c, int bs) {
        // chunk c: 32 k-rows x 320 fp16 = 1280 16B segments
        const uint32_t dstBase = sbase + B_OFF + (uint32_t)bs * B_STAGE;
        #pragma unroll
        for (int j = 0; j < 5; j++) {
            int s  = tid + j * 256;          // 0..1279
            int r  = s / 40;                 // 0..31
            int sg = s % 40;                 // 0..39
            const __half* src = g_Bh + ((size_t)(c * 32 + r) * NCOLS + sg * 8);
            uint32_t dst = dstBase + (uint32_t)(r * B_ROW + sg * 16);
            CP_ASYNC16(dst, src);
        }
    };
    auto ldgA = [&](int c) {
        #pragma unroll
        for (int j = 0; j < 2; j++) {
            int kg = c * 32 + akq + j * 4;
            float4 v = make_float4(0.f, 0.f, 0.f, 0.f);
            if (kg < LDIM)           v = *(const float4*)(sbjRow + kg);
            else if (kg < 2 * LDIM)  v = *(const float4*)(objRow + (kg - LDIM));
            x[j] = v;
        }
    };
    auto stsA = [&](int as) {
        const uint32_t dstA = sbase + A_OFF + (uint32_t)as * A_STAGE + aStsOff;
        uint32_t hw[4];
        #pragma unroll
        for (int j = 0; j < 2; j++) {
            float v0 = fmaxf(x[j].x, 0.f), v1 = fmaxf(x[j].y, 0.f);
            float v2 = fmaxf(x[j].z, 0.f), v3 = fmaxf(x[j].w, 0.f);
            __half2 p01 = __floats2half2_rn(v0, v1);
            __half2 p23 = __floats2half2_rn(v2, v3);
            memcpy(&hw[j * 2],     &p01, 4);
            memcpy(&hw[j * 2 + 1], &p23, 4);
        }
        asm volatile("st.shared.v4.b32 [%0], {%1,%2,%3,%4};" ::
            "r"(dstA), "r"(hw[0]), "r"(hw[1]), "r"(hw[2]), "r"(hw[3]));
    };

    // -------- pipeline prologue --------
    cpB(0, 0); CP_COMMIT();
    cpB(1, 1); CP_COMMIT();
    ldgA(0);
    stsA(0);
    ldgA(1);
    CP_WAIT1();          // B(0) resident
    __syncthreads();

    // -------- main K loop --------
    #pragma unroll 1
    for (int c = 0; c < NCHUNKS; c++) {
        const int as = c & 1;
        const int bs = c % 3;
        const uint32_t AH = sbase + A_OFF + (uint32_t)as * A_STAGE + (uint32_t)(m0 * 80) + aoff;
        const uint32_t BH = sbase + B_OFF + (uint32_t)bs * B_STAGE + (uint32_t)(n0 * 2) + boff;

        // Preload A fragments for BOTH k16 halves of this 32-deep chunk
        uint32_t ah[16];
        ldsm_x4(ah,      AH);               // ks0, mi0
        ldsm_x4(ah + 4,  AH + 1280);        // ks0, mi1
        ldsm_x4(ah + 8,  AH + 32);          // ks1, mi0
        ldsm_x4(ah + 12, AH + 1280 + 32);   // ks1, mi1

        #pragma unroll
        for (int g = 0; g < 5; g++) {
            uint32_t bh[8];
            ldsm_x4_t(bh,     BH + g * 32);                 // ks0
            ldsm_x4_t(bh + 4, BH + g * 32 + 16 * B_ROW);    // ks1
            // ks0 across all 4 accumulators (independent)
            mma16816h(acc[0][2 * g],     ah,      bh);
            mma16816h(acc[0][2 * g + 1], ah,      bh + 2);
            mma16816h(acc[1][2 * g],     ah + 4,  bh);
            mma16816h(acc[1][2 * g + 1], ah + 4,  bh + 2);
            // ks1 across all 4 accumulators (C-reuse distance = 4)
            mma16816h(acc[0][2 * g],     ah + 8,  bh + 4);
            mma16816h(acc[0][2 * g + 1], ah + 8,  bh + 6);
            mma16816h(acc[1][2 * g],     ah + 12, bh + 4);
            mma16816h(acc[1][2 * g + 1], ah + 12, bh + 6);
        }
        if (c + 1 < NCHUNKS) stsA((c + 1) & 1);
        if (c + 2 < NCHUNKS) {
            ldgA(c + 2);
            cpB(c + 2, (c + 2) % 3); CP_COMMIT();
            CP_WAIT1();
        } else {
            CP_WAIT0();
        }
        __syncthreads();
    }

    // -------- epilogue: bias + relu + w2 dot --------
    {
        float p[2][2];
        p[0][0] = p[0][1] = p[1][0] = p[1][1] = 0.f;
        #pragma unroll
        for (int ni = 0; ni < 10; ni++) {
            int gcol = n0 + ni * 8 + tid4 * 2;
            float w2a = w2s[gcol], w2b = w2s[gcol + 1];
            float b1a = b1s[gcol], b1b = b1s[gcol + 1];
            #pragma unroll
            for (int mi = 0; mi < 2; mi++) {
                float* C = acc[mi][ni];
                p[mi][0] = fmaf(fmaxf(C[0] + b1a, 0.f), w2a,
                            fmaf(fmaxf(C[1] + b1b, 0.f), w2b, p[mi][0]));
                p[mi][1] = fmaf(fmaxf(C[2] + b1a, 0.f), w2a,
                            fmaf(fmaxf(C[3] + b1b, 0.f), w2b, p[mi][1]));
            }
        }
        #pragma unroll
        for (int mi = 0; mi < 2; mi++)
            #pragma unroll
            for (int h = 0; h < 2; h++) {
                p[mi][h] += __shfl_xor_sync(0xFFFFFFFFu, p[mi][h], 1);
                p[mi][h] += __shfl_xor_sync(0xFFFFFFFFu, p[mi][h], 2);
            }
        if (tid4 == 0) {
            #pragma unroll
            for (int mi = 0; mi < 2; mi++)
                #pragma unroll
                for (int h = 0; h < 2; h++)
                    atomicAdd(&sdot[m0 + mi * 16 + h * 8 + gid], p[mi][h]);
        }
    }
    __syncthreads();

    // -------- final epilogue --------
    if (tid < 64) {
        const int r = tid;
        const int i = row0 + r;
        float lan = sdot[r] + __ldg(&b2[0]);

        const float* rp = rlts + (size_t)i * 15;
        float label = rp[4];
        float sx1 = rp[5],  sy1 = rp[6],  sx2 = rp[7],  sy2 = rp[8];
        float ox1 = rp[10], oy1 = rp[11], ox2 = rp[12], oy2 = rp[13];
        float sw = sx2 - sx1, sh = sy2 - sy1, ow = ox2 - ox1, oh = oy2 - oy1;
        float box = __ldg(&spa_b[0]);
        box += ((sx1 - ox1) / sw) * __ldg(&spa_w[0]);
        box += ((sy1 - oy1) / sh) * __ldg(&spa_w[1]);
        box += logf(sw / ow)      * __ldg(&spa_w[2]);
        box += logf(sh / oh)      * __ldg(&spa_w[3]);
        box += ((ox1 - sx1) / ow) * __ldg(&spa_w[4]);
        box += ((oy1 - sy1) / oh) * __ldg(&spa_w[5]);
        box += logf(ow / sw)      * __ldg(&spa_w[6]);
        box += logf(oh / sh)      * __ldg(&spa_w[7]);

        float xs = lan + box;
        float sc = 1.f / (1.f + expf(-xs));
        out[i] = sc;

        bool pos = label > 0.f;
        float log_s  = fmaxf(logf(fmaxf(sc,       1e-12f)), -100.f);
        float log_1s = fmaxf(logf(fmaxf(1.f - sc, 1e-12f)), -100.f);
        float term = -(pos ? log_s : log_1s);

        unsigned m_pos  = __ballot_sync(0xFFFFFFFFu, pos);
        unsigned m_posr = __ballot_sync(0xFFFFFFFFu, (!pos) && (sc >= 0.5f));
        unsigned m_negr = __ballot_sync(0xFFFFFFFFu, pos && (sc < 0.5f));
        #pragma unroll
        for (int o = 16; o > 0; o >>= 1) term += __shfl_xor_sync(0xFFFFFFFFu, term, o);
        if ((tid & 31) == 0) {
            atomicAdd(&g_cnt_pos,  (unsigned)__popc(m_pos));
            atomicAdd(&g_cnt_posr, (unsigned)__popc(m_posr));
            atomicAdd(&g_cnt_negr, (unsigned)__popc(m_negr));
            atomicAdd(&g_loss_sum, (double)term);
        }
    }
}

// ============================================================================
// Kernel 3: finalize
// ============================================================================
__global__ void finalize_kernel(float* __restrict__ out, int out_size) {
    if (threadIdx.x == 0 && blockIdx.x == 0) {
        float Npos  = (float)g_cnt_pos;
        float Nneg  = (float)(NROWS - (int)g_cnt_pos);
        float Nposr = (float)g_cnt_posr;
        float Nnegr = (float)g_cnt_negr;
        float loss  = (float)(g_loss_sum / (double)NROWS);
        if (out_size >= NROWS + 4) {
            out[NROWS + 0] = loss;
            out[NROWS + 1] = Nposr / Npos;
            out[NROWS + 2] = Nnegr / Nneg;
            out[NROWS + 3] = (Nposr + Nnegr) / (Npos + Nneg);
        }
    }
    int idx = NROWS + 4 + (int)(blockIdx.x * blockDim.x + threadIdx.x);
    if (idx < out_size) out[idx] = 0.f;
}

// ============================================================================
// Launch
// ============================================================================
extern "C" void kernel_launch(void* const* d_in, const int* in_sizes, int n_in,
                              void* d_out, int out_size) {
    const float* sbj   = (const float*)d_in[0];
    const float* obj   = (const float*)d_in[1];
    const float* rlts  = (const float*)d_in[2];
    const float* spa_w = (const float*)d_in[3];
    const float* spa_b = (const float*)d_in[4];
    const float* w1    = (const float*)d_in[5];
    const float* b1    = (const float*)d_in[6];
    const float* w2    = (const float*)d_in[7];
    const float* b2    = (const float*)d_in[8];
    float* out = (float*)d_out;

    cudaFuncSetAttribute(gemm_kernel, cudaFuncAttributeMaxDynamicSharedMemorySize, SMEM_TOTAL);

    const int prep_total = KTOT * (NCOLS / 4);
    prep_kernel<<<(prep_total + 255) / 256, 256>>>(w1);
    gemm_kernel<<<NROWS / 64, 256, SMEM_TOTAL>>>(sbj, obj, rlts, spa_w, spa_b, b1, w2, b2, out);
    finalize_kernel<<<1, 256>>>(out, out_size);
}